// round 2
// baseline (speedup 1.0000x reference)
#include <cuda_runtime.h>
#include <math.h>

// Scratch (device globals — no allocations allowed).
// g_ctx layout: [e][row][h] with e in 0..47 (q heads 0-15, k heads 16-31, v heads 32-47),
//               row = b*2048 + l (8192 rows), h = 0..63.
__device__ float g_ctx[48ull * 8192ull * 64ull];   // ~100.7 MB
__device__ float g_av[8192ull * 1024ull];          // ~33.5 MB

// ---------------------------------------------------------------------------
// Kernel 1: QKV ensemble projection.
// ctx[e][row][h] = sum_d x[row][d] * Wqkv[e][d][h] + bqkv[e][h]
// Per block: 128 rows x 64 cols (one e). K=1024, k-step 16. 256 threads, 8x4 microtile.
// ---------------------------------------------------------------------------
__global__ __launch_bounds__(256)
void qkv_kernel(const float* __restrict__ x,
                const float* __restrict__ W,
                const float* __restrict__ bias)
{
    __shared__ float As[16][128];   // [k][row]
    __shared__ float Bs[16][64];    // [k][h]

    const int e   = blockIdx.y;
    const int m0  = blockIdx.x * 128;
    const int tid = threadIdx.x;
    const int tx  = tid & 15;       // col group (4 cols)
    const int ty  = tid >> 4;       // row group (8 rows)

    float acc[8][4];
    #pragma unroll
    for (int i = 0; i < 8; ++i)
        #pragma unroll
        for (int j = 0; j < 4; ++j) acc[i][j] = 0.f;

    const float* Wb = W + (size_t)e * 1024 * 64;

    for (int k0 = 0; k0 < 1024; k0 += 16) {
        // A tile: 128 rows x 16 k, float4 along k, store transposed
        #pragma unroll
        for (int r = 0; r < 2; ++r) {
            int idx = tid + r * 256;
            int row = idx >> 2;
            int c4  = (idx & 3) * 4;
            float4 v = *(const float4*)(x + (size_t)(m0 + row) * 1024 + k0 + c4);
            As[c4 + 0][row] = v.x; As[c4 + 1][row] = v.y;
            As[c4 + 2][row] = v.z; As[c4 + 3][row] = v.w;
        }
        // B tile: 16 k-rows x 64 cols (h contiguous in Wqkv) — direct float4
        {
            int kk = tid >> 4;
            int c4 = (tid & 15) * 4;
            float4 v = *(const float4*)(Wb + (size_t)(k0 + kk) * 64 + c4);
            *(float4*)&Bs[kk][c4] = v;
        }
        __syncthreads();

        #pragma unroll
        for (int k = 0; k < 16; ++k) {
            float4 a0 = *(float4*)&As[k][ty * 8];
            float4 a1 = *(float4*)&As[k][ty * 8 + 4];
            float4 b  = *(float4*)&Bs[k][tx * 4];
            float a[8] = {a0.x, a0.y, a0.z, a0.w, a1.x, a1.y, a1.z, a1.w};
            float bb[4] = {b.x, b.y, b.z, b.w};
            #pragma unroll
            for (int i = 0; i < 8; ++i)
                #pragma unroll
                for (int j = 0; j < 4; ++j)
                    acc[i][j] += a[i] * bb[j];
        }
        __syncthreads();
    }

    float4 bv = *(const float4*)(bias + e * 64 + tx * 4);
    float bb[4] = {bv.x, bv.y, bv.z, bv.w};
    float* outp = g_ctx + ((size_t)e * 8192 + m0) * 64;
    #pragma unroll
    for (int i = 0; i < 8; ++i) {
        int row = ty * 8 + i;
        float4 o = make_float4(acc[i][0] + bb[0], acc[i][1] + bb[1],
                               acc[i][2] + bb[2], acc[i][3] + bb[3]);
        *(float4*)(outp + (size_t)row * 64 + tx * 4) = o;
    }
}

// ---------------------------------------------------------------------------
// Kernel 2: flash attention, fp32. One block = (head, batch, 64-query block).
// scale = +sqrt(64) = 8, folded into Q at load. Online softmax.
// smem: Qs [d][qi] (Q*8, transposed), KPs = union of K[d][kj] / P[qi][kj], Vs [kj][d].
// 3 * 16KB = 48KB static shared (exactly the limit).
// ---------------------------------------------------------------------------
__global__ __launch_bounds__(256)
void attn_kernel()
{
    __shared__ float Qs[64][64];    // [d][qi]
    __shared__ float KPs[64][64];   // K: [d][kj] during S; P: [qi][kj] during PV
    __shared__ float Vs[64][64];    // [kj][d]

    const int hb  = blockIdx.y;
    const int hd  = hb >> 2;
    const int b   = hb & 3;
    const int q0  = blockIdx.x * 64;
    const int tid = threadIdx.x;
    const int tx  = tid & 15;       // 4 cols each (kj for S, d for PV)
    const int ty  = tid >> 4;       // 4 rows each (qi)

    const float* Qg = g_ctx + ((size_t)hd * 8192 + b * 2048 + q0) * 64;
    const float* Kg = g_ctx + ((size_t)(16 + hd) * 8192 + (size_t)b * 2048) * 64;
    const float* Vg = g_ctx + ((size_t)(32 + hd) * 8192 + (size_t)b * 2048) * 64;

    // Load Q transposed, pre-scaled by 8
    #pragma unroll
    for (int r = 0; r < 1; ++r) {
        int idx = tid;                     // 256 threads x 4 iterations
        #pragma unroll
        for (int rr = 0; rr < 4; ++rr) {
            int id2 = idx + rr * 256;
            int row = id2 >> 4;
            int c4  = (id2 & 15) * 4;
            float4 v = *(const float4*)(Qg + (size_t)row * 64 + c4);
            Qs[c4 + 0][row] = v.x * 8.f; Qs[c4 + 1][row] = v.y * 8.f;
            Qs[c4 + 2][row] = v.z * 8.f; Qs[c4 + 3][row] = v.w * 8.f;
        }
    }

    float m[4], l[4], O[4][4];
    #pragma unroll
    for (int i = 0; i < 4; ++i) {
        m[i] = -1e30f; l[i] = 0.f;
        #pragma unroll
        for (int j = 0; j < 4; ++j) O[i][j] = 0.f;
    }

    for (int j0 = 0; j0 < 2048; j0 += 64) {
        __syncthreads();   // previous PV done; safe to overwrite KPs/Vs

        // Load K chunk (transposed) and V chunk (natural)
        #pragma unroll
        for (int rr = 0; rr < 4; ++rr) {
            int id2 = tid + rr * 256;
            int row = id2 >> 4;
            int c4  = (id2 & 15) * 4;
            float4 kv = *(const float4*)(Kg + (size_t)(j0 + row) * 64 + c4);
            KPs[c4 + 0][row] = kv.x; KPs[c4 + 1][row] = kv.y;
            KPs[c4 + 2][row] = kv.z; KPs[c4 + 3][row] = kv.w;
            float4 vv = *(const float4*)(Vg + (size_t)(j0 + row) * 64 + c4);
            *(float4*)&Vs[row][c4] = vv;
        }
        __syncthreads();

        // S[qi][kj] = (8*Q) . K
        float s[4][4];
        #pragma unroll
        for (int i = 0; i < 4; ++i)
            #pragma unroll
            for (int j = 0; j < 4; ++j) s[i][j] = 0.f;

        #pragma unroll
        for (int d = 0; d < 64; ++d) {
            float4 a = *(float4*)&Qs[d][ty * 4];
            float4 bq = *(float4*)&KPs[d][tx * 4];
            float aa[4] = {a.x, a.y, a.z, a.w};
            float bb[4] = {bq.x, bq.y, bq.z, bq.w};
            #pragma unroll
            for (int i = 0; i < 4; ++i)
                #pragma unroll
                for (int j = 0; j < 4; ++j)
                    s[i][j] += aa[i] * bb[j];
        }
        __syncthreads();   // all K reads complete before P overwrites KPs

        // Online softmax per row; write P (natural layout [qi][kj], float4 = conflict-free)
        #pragma unroll
        for (int i = 0; i < 4; ++i) {
            float rmax = fmaxf(fmaxf(s[i][0], s[i][1]), fmaxf(s[i][2], s[i][3]));
            #pragma unroll
            for (int off = 8; off >= 1; off >>= 1)
                rmax = fmaxf(rmax, __shfl_xor_sync(0xffffffffu, rmax, off));
            float mnew = fmaxf(m[i], rmax);
            float corr = __expf(m[i] - mnew);
            float rsum = 0.f;
            #pragma unroll
            for (int j = 0; j < 4; ++j) {
                s[i][j] = __expf(s[i][j] - mnew);
                rsum += s[i][j];
            }
            #pragma unroll
            for (int off = 8; off >= 1; off >>= 1)
                rsum += __shfl_xor_sync(0xffffffffu, rsum, off);
            l[i] = l[i] * corr + rsum;
            m[i] = mnew;
            #pragma unroll
            for (int j = 0; j < 4; ++j) O[i][j] *= corr;
            *(float4*)&KPs[ty * 4 + i][tx * 4] =
                make_float4(s[i][0], s[i][1], s[i][2], s[i][3]);
        }
        __syncthreads();

        // O += P @ V, unrolled by 4 along kj
        #pragma unroll
        for (int kj = 0; kj < 64; kj += 4) {
            float4 p0 = *(float4*)&KPs[ty * 4 + 0][kj];
            float4 p1 = *(float4*)&KPs[ty * 4 + 1][kj];
            float4 p2 = *(float4*)&KPs[ty * 4 + 2][kj];
            float4 p3 = *(float4*)&KPs[ty * 4 + 3][kj];
            float4 v0 = *(float4*)&Vs[kj + 0][tx * 4];
            float4 v1 = *(float4*)&Vs[kj + 1][tx * 4];
            float4 v2 = *(float4*)&Vs[kj + 2][tx * 4];
            float4 v3 = *(float4*)&Vs[kj + 3][tx * 4];
            float pp[4][4] = {{p0.x, p0.y, p0.z, p0.w},
                              {p1.x, p1.y, p1.z, p1.w},
                              {p2.x, p2.y, p2.z, p2.w},
                              {p3.x, p3.y, p3.z, p3.w}};
            float vv[4][4] = {{v0.x, v0.y, v0.z, v0.w},
                              {v1.x, v1.y, v1.z, v1.w},
                              {v2.x, v2.y, v2.z, v2.w},
                              {v3.x, v3.y, v3.z, v3.w}};
            #pragma unroll
            for (int i = 0; i < 4; ++i)
                #pragma unroll
                for (int j = 0; j < 4; ++j)
                    O[i][j] += pp[i][0] * vv[0][j] + pp[i][1] * vv[1][j]
                             + pp[i][2] * vv[2][j] + pp[i][3] * vv[3][j];
        }
    }

    // Final normalize, write av[b*2048+q0+qi][hd*64 + d]
    float* outp = g_av + (size_t)(b * 2048 + q0) * 1024 + hd * 64;
    #pragma unroll
    for (int i = 0; i < 4; ++i) {
        float inv = 1.f / l[i];
        float4 o = make_float4(O[i][0] * inv, O[i][1] * inv,
                               O[i][2] * inv, O[i][3] * inv);
        *(float4*)(outp + (size_t)(ty * 4 + i) * 1024 + tx * 4) = o;
    }
}

// ---------------------------------------------------------------------------
// Kernel 3: output projection. out[row][n] = sum_j av[row][j] * Wp[n][j] + bp[n]
// Same tiling as kernel 1; Wp rows (j contiguous) loaded transposed into smem.
// ---------------------------------------------------------------------------
__global__ __launch_bounds__(256)
void proj_kernel(const float* __restrict__ Wp,
                 const float* __restrict__ bp,
                 float* __restrict__ out)
{
    __shared__ float As[16][128];   // [k][row]
    __shared__ float Bs[16][64];    // [k][n]

    const int n0  = blockIdx.y * 64;
    const int m0  = blockIdx.x * 128;
    const int tid = threadIdx.x;
    const int tx  = tid & 15;
    const int ty  = tid >> 4;

    float acc[8][4];
    #pragma unroll
    for (int i = 0; i < 8; ++i)
        #pragma unroll
        for (int j = 0; j < 4; ++j) acc[i][j] = 0.f;

    for (int k0 = 0; k0 < 1024; k0 += 16) {
        #pragma unroll
        for (int r = 0; r < 2; ++r) {
            int idx = tid + r * 256;
            int row = idx >> 2;
            int c4  = (idx & 3) * 4;
            float4 v = *(const float4*)(g_av + (size_t)(m0 + row) * 1024 + k0 + c4);
            As[c4 + 0][row] = v.x; As[c4 + 1][row] = v.y;
            As[c4 + 2][row] = v.z; As[c4 + 3][row] = v.w;
        }
        {
            int n  = tid >> 2;                 // 0..63
            int c4 = (tid & 3) * 4;            // k offset
            float4 v = *(const float4*)(Wp + (size_t)(n0 + n) * 1024 + k0 + c4);
            Bs[c4 + 0][n] = v.x; Bs[c4 + 1][n] = v.y;
            Bs[c4 + 2][n] = v.z; Bs[c4 + 3][n] = v.w;
        }
        __syncthreads();

        #pragma unroll
        for (int k = 0; k < 16; ++k) {
            float4 a0 = *(float4*)&As[k][ty * 8];
            float4 a1 = *(float4*)&As[k][ty * 8 + 4];
            float4 b  = *(float4*)&Bs[k][tx * 4];
            float a[8] = {a0.x, a0.y, a0.z, a0.w, a1.x, a1.y, a1.z, a1.w};
            float bb[4] = {b.x, b.y, b.z, b.w};
            #pragma unroll
            for (int i = 0; i < 8; ++i)
                #pragma unroll
                for (int j = 0; j < 4; ++j)
                    acc[i][j] += a[i] * bb[j];
        }
        __syncthreads();
    }

    float4 bv = *(const float4*)(bp + n0 + tx * 4);
    float bb[4] = {bv.x, bv.y, bv.z, bv.w};
    #pragma unroll
    for (int i = 0; i < 8; ++i) {
        int row = m0 + ty * 8 + i;
        float4 o = make_float4(acc[i][0] + bb[0], acc[i][1] + bb[1],
                               acc[i][2] + bb[2], acc[i][3] + bb[3]);
        *(float4*)(out + (size_t)row * 1024 + n0 + tx * 4) = o;
    }
}

// ---------------------------------------------------------------------------
extern "C" void kernel_launch(void* const* d_in, const int* in_sizes, int n_in,
                              void* d_out, int out_size)
{
    const float* x    = (const float*)d_in[0];   // (4, 2048, 1024)
    const float* Wqkv = (const float*)d_in[1];   // (48, 1024, 64)
    const float* bqkv = (const float*)d_in[2];   // (48, 64)
    const float* Wp   = (const float*)d_in[3];   // (1024, 1024)
    const float* bp   = (const float*)d_in[4];   // (1024,)
    float* out = (float*)d_out;                  // (4, 2048, 1024)

    qkv_kernel<<<dim3(64, 48), 256>>>(x, Wqkv, bqkv);
    attn_kernel<<<dim3(32, 64), 256>>>();        // x: 32 q-blocks, y: head*4+batch
    proj_kernel<<<dim3(64, 16), 256>>>(Wp, bp, out);
}

// round 4
// speedup vs baseline: 1.2830x; 1.2830x over previous
#include <cuda_runtime.h>
#include <cuda_bf16.h>
#include <stdint.h>
#include <math.h>

// ============================================================================
// Scratch (device globals — no allocations allowed).
// ============================================================================
__device__ float g_ctx[48ull * 8192ull * 64ull];   // [e][row][h], ~100.7 MB
__device__ float g_av [8192ull * 1024ull];         // attention output, 33.5 MB
__device__ float g_wt [48ull * 64ull * 1024ull];   // Wqkv transposed [e][h][d]

// ============================================================================
// mma.sync helpers (sm_80-era PTX — compiles for plain compute_103)
// ============================================================================
__device__ __forceinline__ uint32_t smem_u32(const void* p) {
    uint32_t a;
    asm("{ .reg .u64 t; cvta.to.shared.u64 t, %1; cvt.u32.u64 %0, t; }"
        : "=r"(a) : "l"(p));
    return a;
}

__device__ __forceinline__ void ldmatrix_x4(uint32_t& r0, uint32_t& r1,
                                            uint32_t& r2, uint32_t& r3,
                                            uint32_t addr) {
    asm volatile("ldmatrix.sync.aligned.m8n8.x4.shared.b16 {%0,%1,%2,%3}, [%4];"
                 : "=r"(r0), "=r"(r1), "=r"(r2), "=r"(r3) : "r"(addr));
}

__device__ __forceinline__ void mma_bf16(float* c,
                                         uint32_t a0, uint32_t a1, uint32_t a2, uint32_t a3,
                                         uint32_t b0, uint32_t b1) {
    asm volatile("mma.sync.aligned.m16n8k16.row.col.f32.bf16.bf16.f32 "
                 "{%0,%1,%2,%3}, {%4,%5,%6,%7}, {%8,%9}, {%0,%1,%2,%3};"
                 : "+f"(c[0]), "+f"(c[1]), "+f"(c[2]), "+f"(c[3])
                 : "r"(a0), "r"(a1), "r"(a2), "r"(a3), "r"(b0), "r"(b1));
}

// ============================================================================
// Kernel 0: transpose Wqkv [48][1024][64] -> g_wt [48][64][1024]
// ============================================================================
__global__ void transpose_w(const float* __restrict__ W) {
    __shared__ float t[32][33];
    const int e  = blockIdx.z;
    const int k0 = blockIdx.x * 32;
    const int h0 = blockIdx.y * 32;
    const int tx = threadIdx.x, ty = threadIdx.y;
    #pragma unroll
    for (int i = 0; i < 32; i += 8)
        t[ty + i][tx] = W[(size_t)e * 65536 + (size_t)(k0 + ty + i) * 64 + h0 + tx];
    __syncthreads();
    #pragma unroll
    for (int i = 0; i < 32; i += 8)
        g_wt[(size_t)e * 65536 + (size_t)(h0 + ty + i) * 1024 + k0 + tx] = t[tx][ty + i];
}

// ============================================================================
// Kernel 1: split-bf16 tensor-core GEMM (mma.sync).
//   C[grp][m][n] = sum_k A[m][k] * B[grp*64+n][k] + bias[grp*64+n]
//   A [8192 x 1024] fp32 row-major; B K-major rows of 1024 (g_wt / Wp).
//   CTA 128x64, 8 warps (4m x 2n), warp tile 32x32, BK=32.
//   Split at load: hi = bf16(x), lo = bf16(x - hi); 3 mma terms per k16.
// ============================================================================
#define LDA   80u          // smem row stride bytes (32 bf16 + 8 pad)
#define SA_HI 0u
#define SA_LO 10240u
#define SB_HI 20480u
#define SB_LO 25600u

__global__ __launch_bounds__(256)
void gemm_mma(const float* __restrict__ A, const float* __restrict__ B,
              const float* __restrict__ bias, float* __restrict__ C,
              int ldC, size_t gStrideC)
{
    __shared__ char smem[30720];
    const uint32_t sb  = smem_u32(smem);
    const int tid  = threadIdx.x;
    const int lane = tid & 31;
    const int wid  = tid >> 5;
    const int wm   = wid & 3;       // m block (32 rows)
    const int wn   = wid >> 2;      // n block (32 cols)
    const int m0   = blockIdx.x * 128;
    const int grp  = blockIdx.y;

    const float* Bg = B + (size_t)grp * 64 * 1024;

    float acc[2][4][4];
    #pragma unroll
    for (int mt = 0; mt < 2; ++mt)
        #pragma unroll
        for (int nt = 0; nt < 4; ++nt)
            #pragma unroll
            for (int i = 0; i < 4; ++i) acc[mt][nt][i] = 0.f;

    // ldmatrix thread addresses
    const int a_row = wm * 32 + (lane & 7) + ((lane >> 3) & 1) * 8;
    const uint32_t a_kb = (uint32_t)(lane >> 4) * 16u;
    const uint32_t aHi = sb + SA_HI + (uint32_t)a_row * LDA + a_kb;
    const uint32_t aLo = sb + SA_LO + (uint32_t)a_row * LDA + a_kb;

    const int b_row = wn * 32 + (lane & 7) + (lane >> 4) * 8;
    const uint32_t b_kb = (uint32_t)((lane >> 3) & 1) * 16u;
    const uint32_t bHi = sb + SB_HI + (uint32_t)b_row * LDA + b_kb;
    const uint32_t bLo = sb + SB_LO + (uint32_t)b_row * LDA + b_kb;

    for (int k0 = 0; k0 < 1024; k0 += 32) {
        __syncthreads();   // previous iter's ldmatrix reads complete

        // ---- A tile: 128 rows x 32 k (fp32 -> bf16 hi/lo) ----
        #pragma unroll
        for (int i = 0; i < 4; ++i) {
            int idx = tid + i * 256;             // < 1024
            int row = idx >> 3;
            int c4  = idx & 7;
            float4 v = *(const float4*)(A + (size_t)(m0 + row) * 1024 + k0 + c4 * 4);
            __nv_bfloat16 hx = __float2bfloat16(v.x), hy = __float2bfloat16(v.y);
            __nv_bfloat16 hz = __float2bfloat16(v.z), hw = __float2bfloat16(v.w);
            __nv_bfloat16 lx = __float2bfloat16(v.x - __bfloat162float(hx));
            __nv_bfloat16 ly = __float2bfloat16(v.y - __bfloat162float(hy));
            __nv_bfloat16 lz = __float2bfloat16(v.z - __bfloat162float(hz));
            __nv_bfloat16 lw = __float2bfloat16(v.w - __bfloat162float(hw));
            uint32_t off = (uint32_t)row * LDA + (uint32_t)c4 * 8u;
            *(__nv_bfloat162*)(smem + SA_HI + off)     = __nv_bfloat162(hx, hy);
            *(__nv_bfloat162*)(smem + SA_HI + off + 4) = __nv_bfloat162(hz, hw);
            *(__nv_bfloat162*)(smem + SA_LO + off)     = __nv_bfloat162(lx, ly);
            *(__nv_bfloat162*)(smem + SA_LO + off + 4) = __nv_bfloat162(lz, lw);
        }
        // ---- B tile: 64 rows x 32 k ----
        #pragma unroll
        for (int i = 0; i < 2; ++i) {
            int idx = tid + i * 256;             // < 512
            int row = idx >> 3;
            int c4  = idx & 7;
            float4 v = *(const float4*)(Bg + (size_t)row * 1024 + k0 + c4 * 4);
            __nv_bfloat16 hx = __float2bfloat16(v.x), hy = __float2bfloat16(v.y);
            __nv_bfloat16 hz = __float2bfloat16(v.z), hw = __float2bfloat16(v.w);
            __nv_bfloat16 lx = __float2bfloat16(v.x - __bfloat162float(hx));
            __nv_bfloat16 ly = __float2bfloat16(v.y - __bfloat162float(hy));
            __nv_bfloat16 lz = __float2bfloat16(v.z - __bfloat162float(hz));
            __nv_bfloat16 lw = __float2bfloat16(v.w - __bfloat162float(hw));
            uint32_t off = (uint32_t)row * LDA + (uint32_t)c4 * 8u;
            *(__nv_bfloat162*)(smem + SB_HI + off)     = __nv_bfloat162(hx, hy);
            *(__nv_bfloat162*)(smem + SB_HI + off + 4) = __nv_bfloat162(hz, hw);
            *(__nv_bfloat162*)(smem + SB_LO + off)     = __nv_bfloat162(lx, ly);
            *(__nv_bfloat162*)(smem + SB_LO + off + 4) = __nv_bfloat162(lz, lw);
        }
        __syncthreads();

        #pragma unroll
        for (int ks = 0; ks < 2; ++ks) {
            const uint32_t koff = (uint32_t)ks * 32u;   // 16 bf16 = 32 bytes

            uint32_t ahi[2][4], alo[2][4];
            #pragma unroll
            for (int mt = 0; mt < 2; ++mt) {
                ldmatrix_x4(ahi[mt][0], ahi[mt][1], ahi[mt][2], ahi[mt][3],
                            aHi + (uint32_t)mt * 16u * LDA + koff);
                ldmatrix_x4(alo[mt][0], alo[mt][1], alo[mt][2], alo[mt][3],
                            aLo + (uint32_t)mt * 16u * LDA + koff);
            }
            uint32_t bhi[4][2], blo[4][2];
            #pragma unroll
            for (int ntp = 0; ntp < 2; ++ntp) {
                uint32_t r0, r1, r2, r3;
                ldmatrix_x4(r0, r1, r2, r3, bHi + (uint32_t)ntp * 16u * LDA + koff);
                bhi[ntp * 2][0] = r0; bhi[ntp * 2][1] = r1;
                bhi[ntp * 2 + 1][0] = r2; bhi[ntp * 2 + 1][1] = r3;
                ldmatrix_x4(r0, r1, r2, r3, bLo + (uint32_t)ntp * 16u * LDA + koff);
                blo[ntp * 2][0] = r0; blo[ntp * 2][1] = r1;
                blo[ntp * 2 + 1][0] = r2; blo[ntp * 2 + 1][1] = r3;
            }

            #pragma unroll
            for (int mt = 0; mt < 2; ++mt)
                #pragma unroll
                for (int nt = 0; nt < 4; ++nt) {
                    mma_bf16(acc[mt][nt], ahi[mt][0], ahi[mt][1], ahi[mt][2], ahi[mt][3],
                             bhi[nt][0], bhi[nt][1]);
                    mma_bf16(acc[mt][nt], ahi[mt][0], ahi[mt][1], ahi[mt][2], ahi[mt][3],
                             blo[nt][0], blo[nt][1]);
                    mma_bf16(acc[mt][nt], alo[mt][0], alo[mt][1], alo[mt][2], alo[mt][3],
                             bhi[nt][0], bhi[nt][1]);
                }
        }
    }

    // ---- epilogue ----
    const int g  = lane >> 2;
    const int tg = lane & 3;
    const float* bp = bias + (size_t)grp * 64;
    float* Cp = C + (size_t)grp * gStrideC;
    #pragma unroll
    for (int mt = 0; mt < 2; ++mt)
        #pragma unroll
        for (int nt = 0; nt < 4; ++nt) {
            int col = wn * 32 + nt * 8 + tg * 2;
            float b0 = bp[col], b1 = bp[col + 1];
            int r0 = m0 + wm * 32 + mt * 16 + g;
            float2 o0 = make_float2(acc[mt][nt][0] + b0, acc[mt][nt][1] + b1);
            float2 o1 = make_float2(acc[mt][nt][2] + b0, acc[mt][nt][3] + b1);
            *(float2*)(Cp + (size_t)r0 * ldC + col)       = o0;
            *(float2*)(Cp + (size_t)(r0 + 8) * ldC + col) = o1;
        }
}

// ============================================================================
// Kernel 2: flash attention, fp32 (unchanged, proven correct).
// ============================================================================
__global__ __launch_bounds__(256)
void attn_kernel()
{
    __shared__ float Qs[64][64];
    __shared__ float KPs[64][64];
    __shared__ float Vs[64][64];

    const int hb  = blockIdx.y;
    const int hd  = hb >> 2;
    const int b   = hb & 3;
    const int q0  = blockIdx.x * 64;
    const int tid = threadIdx.x;
    const int tx  = tid & 15;
    const int ty  = tid >> 4;

    const float* Qg = g_ctx + ((size_t)hd * 8192 + b * 2048 + q0) * 64;
    const float* Kg = g_ctx + ((size_t)(16 + hd) * 8192 + (size_t)b * 2048) * 64;
    const float* Vg = g_ctx + ((size_t)(32 + hd) * 8192 + (size_t)b * 2048) * 64;

    #pragma unroll
    for (int rr = 0; rr < 4; ++rr) {
        int id2 = tid + rr * 256;
        int row = id2 >> 4;
        int c4  = (id2 & 15) * 4;
        float4 v = *(const float4*)(Qg + (size_t)row * 64 + c4);
        Qs[c4 + 0][row] = v.x * 8.f; Qs[c4 + 1][row] = v.y * 8.f;
        Qs[c4 + 2][row] = v.z * 8.f; Qs[c4 + 3][row] = v.w * 8.f;
    }

    float m[4], l[4], O[4][4];
    #pragma unroll
    for (int i = 0; i < 4; ++i) {
        m[i] = -1e30f; l[i] = 0.f;
        #pragma unroll
        for (int j = 0; j < 4; ++j) O[i][j] = 0.f;
    }

    for (int j0 = 0; j0 < 2048; j0 += 64) {
        __syncthreads();
        #pragma unroll
        for (int rr = 0; rr < 4; ++rr) {
            int id2 = tid + rr * 256;
            int row = id2 >> 4;
            int c4  = (id2 & 15) * 4;
            float4 kv = *(const float4*)(Kg + (size_t)(j0 + row) * 64 + c4);
            KPs[c4 + 0][row] = kv.x; KPs[c4 + 1][row] = kv.y;
            KPs[c4 + 2][row] = kv.z; KPs[c4 + 3][row] = kv.w;
            float4 vv = *(const float4*)(Vg + (size_t)(j0 + row) * 64 + c4);
            *(float4*)&Vs[row][c4] = vv;
        }
        __syncthreads();

        float s[4][4];
        #pragma unroll
        for (int i = 0; i < 4; ++i)
            #pragma unroll
            for (int j = 0; j < 4; ++j) s[i][j] = 0.f;

        #pragma unroll
        for (int d = 0; d < 64; ++d) {
            float4 a = *(float4*)&Qs[d][ty * 4];
            float4 bq = *(float4*)&KPs[d][tx * 4];
            float aa[4] = {a.x, a.y, a.z, a.w};
            float bb[4] = {bq.x, bq.y, bq.z, bq.w};
            #pragma unroll
            for (int i = 0; i < 4; ++i)
                #pragma unroll
                for (int j = 0; j < 4; ++j)
                    s[i][j] += aa[i] * bb[j];
        }
        __syncthreads();

        #pragma unroll
        for (int i = 0; i < 4; ++i) {
            float rmax = fmaxf(fmaxf(s[i][0], s[i][1]), fmaxf(s[i][2], s[i][3]));
            #pragma unroll
            for (int off = 8; off >= 1; off >>= 1)
                rmax = fmaxf(rmax, __shfl_xor_sync(0xffffffffu, rmax, off));
            float mnew = fmaxf(m[i], rmax);
            float corr = __expf(m[i] - mnew);
            float rsum = 0.f;
            #pragma unroll
            for (int j = 0; j < 4; ++j) {
                s[i][j] = __expf(s[i][j] - mnew);
                rsum += s[i][j];
            }
            #pragma unroll
            for (int off = 8; off >= 1; off >>= 1)
                rsum += __shfl_xor_sync(0xffffffffu, rsum, off);
            l[i] = l[i] * corr + rsum;
            m[i] = mnew;
            #pragma unroll
            for (int j = 0; j < 4; ++j) O[i][j] *= corr;
            *(float4*)&KPs[ty * 4 + i][tx * 4] =
                make_float4(s[i][0], s[i][1], s[i][2], s[i][3]);
        }
        __syncthreads();

        #pragma unroll
        for (int kj = 0; kj < 64; kj += 4) {
            float4 p0 = *(float4*)&KPs[ty * 4 + 0][kj];
            float4 p1 = *(float4*)&KPs[ty * 4 + 1][kj];
            float4 p2 = *(float4*)&KPs[ty * 4 + 2][kj];
            float4 p3 = *(float4*)&KPs[ty * 4 + 3][kj];
            float4 v0 = *(float4*)&Vs[kj + 0][tx * 4];
            float4 v1 = *(float4*)&Vs[kj + 1][tx * 4];
            float4 v2 = *(float4*)&Vs[kj + 2][tx * 4];
            float4 v3 = *(float4*)&Vs[kj + 3][tx * 4];
            float pp[4][4] = {{p0.x, p0.y, p0.z, p0.w},
                              {p1.x, p1.y, p1.z, p1.w},
                              {p2.x, p2.y, p2.z, p2.w},
                              {p3.x, p3.y, p3.z, p3.w}};
            float vv[4][4] = {{v0.x, v0.y, v0.z, v0.w},
                              {v1.x, v1.y, v1.z, v1.w},
                              {v2.x, v2.y, v2.z, v2.w},
                              {v3.x, v3.y, v3.z, v3.w}};
            #pragma unroll
            for (int i = 0; i < 4; ++i)
                #pragma unroll
                for (int j = 0; j < 4; ++j)
                    O[i][j] += pp[i][0] * vv[0][j] + pp[i][1] * vv[1][j]
                             + pp[i][2] * vv[2][j] + pp[i][3] * vv[3][j];
        }
    }

    float* outp = g_av + (size_t)(b * 2048 + q0) * 1024 + hd * 64;
    #pragma unroll
    for (int i = 0; i < 4; ++i) {
        float inv = 1.f / l[i];
        float4 o = make_float4(O[i][0] * inv, O[i][1] * inv,
                               O[i][2] * inv, O[i][3] * inv);
        *(float4*)(outp + (size_t)(ty * 4 + i) * 1024 + tx * 4) = o;
    }
}

// ============================================================================
extern "C" void kernel_launch(void* const* d_in, const int* in_sizes, int n_in,
                              void* d_out, int out_size)
{
    const float* x    = (const float*)d_in[0];   // (4, 2048, 1024)
    const float* Wqkv = (const float*)d_in[1];   // (48, 1024, 64)
    const float* bqkv = (const float*)d_in[2];   // (48, 64)
    const float* Wp   = (const float*)d_in[3];   // (1024, 1024)
    const float* bp   = (const float*)d_in[4];   // (1024,)
    float* out = (float*)d_out;                  // (4, 2048, 1024)

    float* g_wt_p;   cudaGetSymbolAddress((void**)&g_wt_p,  g_wt);
    float* g_ctx_p;  cudaGetSymbolAddress((void**)&g_ctx_p, g_ctx);
    float* g_av_p;   cudaGetSymbolAddress((void**)&g_av_p,  g_av);

    // 1) transpose Wqkv -> g_wt [48][64][1024]  (B must be K-major)
    transpose_w<<<dim3(32, 2, 48), dim3(32, 8)>>>(Wqkv);

    // 2) QKV: ctx[e] = x @ Wqkv[e] + bqkv[e]   (one ensemble per CTA column)
    gemm_mma<<<dim3(64, 48), 256>>>(x, g_wt_p, bqkv, g_ctx_p,
                                    /*ldC=*/64, /*gStrideC=*/(size_t)8192 * 64);

    // 3) attention (fp32 SIMT)
    attn_kernel<<<dim3(32, 64), 256>>>();

    // 4) proj: out = av @ Wp^T + bp   (16 column-groups of 64)
    gemm_mma<<<dim3(64, 16), 256>>>(g_av_p, Wp, bp, out,
                                    /*ldC=*/1024, /*gStrideC=*/64);
}

// round 5
// speedup vs baseline: 1.6905x; 1.3176x over previous
#include <cuda_runtime.h>
#include <cuda_bf16.h>
#include <stdint.h>
#include <math.h>

// ============================================================================
// Scratch (device globals — no allocations allowed).
// ============================================================================
__device__ float g_ctx[48ull * 8192ull * 64ull];   // [e][row][h], ~100.7 MB
__device__ float g_av [8192ull * 1024ull];         // attention output, 33.5 MB
__device__ float g_wt [48ull * 64ull * 1024ull];   // Wqkv transposed [e][h][d]

// ============================================================================
// mma.sync helpers (sm_80-era PTX — compiles for plain compute_103)
// ============================================================================
__device__ __forceinline__ uint32_t smem_u32(const void* p) {
    uint32_t a;
    asm("{ .reg .u64 t; cvta.to.shared.u64 t, %1; cvt.u32.u64 %0, t; }"
        : "=r"(a) : "l"(p));
    return a;
}

__device__ __forceinline__ void ldmatrix_x4(uint32_t& r0, uint32_t& r1,
                                            uint32_t& r2, uint32_t& r3,
                                            uint32_t addr) {
    asm volatile("ldmatrix.sync.aligned.m8n8.x4.shared.b16 {%0,%1,%2,%3}, [%4];"
                 : "=r"(r0), "=r"(r1), "=r"(r2), "=r"(r3) : "r"(addr));
}

__device__ __forceinline__ void mma_bf16(float* c,
                                         uint32_t a0, uint32_t a1, uint32_t a2, uint32_t a3,
                                         uint32_t b0, uint32_t b1) {
    asm volatile("mma.sync.aligned.m16n8k16.row.col.f32.bf16.bf16.f32 "
                 "{%0,%1,%2,%3}, {%4,%5,%6,%7}, {%8,%9}, {%0,%1,%2,%3};"
                 : "+f"(c[0]), "+f"(c[1]), "+f"(c[2]), "+f"(c[3])
                 : "r"(a0), "r"(a1), "r"(a2), "r"(a3), "r"(b0), "r"(b1));
}

// pack two f32 into bf16x2 (lo = x, hi = y)
__device__ __forceinline__ uint32_t pack_bf16x2(float x, float y) {
    uint32_t r;
    asm("cvt.rn.bf16x2.f32 %0, %1, %2;" : "=r"(r) : "f"(y), "f"(x));
    return r;
}

// fast 2^t for t <= 0, FFMA/ALU only (no MUFU). rel err ~2.5e-6.
__device__ __forceinline__ float exp2_fast(float t) {
    float r = fmaxf(t, -30.f);
    float z = r + 12582912.f;                 // 1.5 * 2^23 magic (round to int)
    int   i = __float_as_int(z);
    float f = r - (z - 12582912.f);           // f in [-0.5, 0.5]
    float p = 1.33335581e-3f;
    p = fmaf(p, f, 9.61812911e-3f);
    p = fmaf(p, f, 5.55041087e-2f);
    p = fmaf(p, f, 2.40226507e-1f);
    p = fmaf(p, f, 6.93147181e-1f);
    p = fmaf(p, f, 1.0f);
    return p * __int_as_float((i + 127) << 23);
}

// split float4 -> packed bf16x2 hi pair + residual lo pair
__device__ __forceinline__ void split4(float4 v, uint32_t& h01, uint32_t& h23,
                                       uint32_t& l01, uint32_t& l23) {
    h01 = pack_bf16x2(v.x, v.y);
    h23 = pack_bf16x2(v.z, v.w);
    float r0 = v.x - __int_as_float(h01 << 16);
    float r1 = v.y - __int_as_float(h01 & 0xFFFF0000u);
    float r2 = v.z - __int_as_float(h23 << 16);
    float r3 = v.w - __int_as_float(h23 & 0xFFFF0000u);
    l01 = pack_bf16x2(r0, r1);
    l23 = pack_bf16x2(r2, r3);
}

// ============================================================================
// Kernel 0: transpose Wqkv [48][1024][64] -> g_wt [48][64][1024]
// ============================================================================
__global__ void transpose_w(const float* __restrict__ W) {
    __shared__ float t[32][33];
    const int e  = blockIdx.z;
    const int k0 = blockIdx.x * 32;
    const int h0 = blockIdx.y * 32;
    const int tx = threadIdx.x, ty = threadIdx.y;
    #pragma unroll
    for (int i = 0; i < 32; i += 8)
        t[ty + i][tx] = W[(size_t)e * 65536 + (size_t)(k0 + ty + i) * 64 + h0 + tx];
    __syncthreads();
    #pragma unroll
    for (int i = 0; i < 32; i += 8)
        g_wt[(size_t)e * 65536 + (size_t)(h0 + ty + i) * 1024 + k0 + tx] = t[tx][ty + i];
}

// ============================================================================
// Kernel 1: split-bf16 tensor-core GEMM (mma.sync) — unchanged, proven.
// ============================================================================
#define LDA   80u
#define SA_HI 0u
#define SA_LO 10240u
#define SB_HI 20480u
#define SB_LO 25600u

__global__ __launch_bounds__(256)
void gemm_mma(const float* __restrict__ A, const float* __restrict__ B,
              const float* __restrict__ bias, float* __restrict__ C,
              int ldC, size_t gStrideC)
{
    __shared__ char smem[30720];
    const uint32_t sb  = smem_u32(smem);
    const int tid  = threadIdx.x;
    const int lane = tid & 31;
    const int wid  = tid >> 5;
    const int wm   = wid & 3;
    const int wn   = wid >> 2;
    const int m0   = blockIdx.x * 128;
    const int grp  = blockIdx.y;

    const float* Bg = B + (size_t)grp * 64 * 1024;

    float acc[2][4][4];
    #pragma unroll
    for (int mt = 0; mt < 2; ++mt)
        #pragma unroll
        for (int nt = 0; nt < 4; ++nt)
            #pragma unroll
            for (int i = 0; i < 4; ++i) acc[mt][nt][i] = 0.f;

    const int a_row = wm * 32 + (lane & 7) + ((lane >> 3) & 1) * 8;
    const uint32_t a_kb = (uint32_t)(lane >> 4) * 16u;
    const uint32_t aHi = sb + SA_HI + (uint32_t)a_row * LDA + a_kb;
    const uint32_t aLo = sb + SA_LO + (uint32_t)a_row * LDA + a_kb;

    const int b_row = wn * 32 + (lane & 7) + (lane >> 4) * 8;
    const uint32_t b_kb = (uint32_t)((lane >> 3) & 1) * 16u;
    const uint32_t bHi = sb + SB_HI + (uint32_t)b_row * LDA + b_kb;
    const uint32_t bLo = sb + SB_LO + (uint32_t)b_row * LDA + b_kb;

    for (int k0 = 0; k0 < 1024; k0 += 32) {
        __syncthreads();

        #pragma unroll
        for (int i = 0; i < 4; ++i) {
            int idx = tid + i * 256;
            int row = idx >> 3;
            int c4  = idx & 7;
            float4 v = *(const float4*)(A + (size_t)(m0 + row) * 1024 + k0 + c4 * 4);
            uint32_t h01, h23, l01, l23;
            split4(v, h01, h23, l01, l23);
            uint32_t off = (uint32_t)row * LDA + (uint32_t)c4 * 8u;
            *(uint2*)(smem + SA_HI + off) = make_uint2(h01, h23);
            *(uint2*)(smem + SA_LO + off) = make_uint2(l01, l23);
        }
        #pragma unroll
        for (int i = 0; i < 2; ++i) {
            int idx = tid + i * 256;
            int row = idx >> 3;
            int c4  = idx & 7;
            float4 v = *(const float4*)(Bg + (size_t)row * 1024 + k0 + c4 * 4);
            uint32_t h01, h23, l01, l23;
            split4(v, h01, h23, l01, l23);
            uint32_t off = (uint32_t)row * LDA + (uint32_t)c4 * 8u;
            *(uint2*)(smem + SB_HI + off) = make_uint2(h01, h23);
            *(uint2*)(smem + SB_LO + off) = make_uint2(l01, l23);
        }
        __syncthreads();

        #pragma unroll
        for (int ks = 0; ks < 2; ++ks) {
            const uint32_t koff = (uint32_t)ks * 32u;

            uint32_t ahi[2][4], alo[2][4];
            #pragma unroll
            for (int mt = 0; mt < 2; ++mt) {
                ldmatrix_x4(ahi[mt][0], ahi[mt][1], ahi[mt][2], ahi[mt][3],
                            aHi + (uint32_t)mt * 16u * LDA + koff);
                ldmatrix_x4(alo[mt][0], alo[mt][1], alo[mt][2], alo[mt][3],
                            aLo + (uint32_t)mt * 16u * LDA + koff);
            }
            uint32_t bhi[4][2], blo[4][2];
            #pragma unroll
            for (int ntp = 0; ntp < 2; ++ntp) {
                uint32_t r0, r1, r2, r3;
                ldmatrix_x4(r0, r1, r2, r3, bHi + (uint32_t)ntp * 16u * LDA + koff);
                bhi[ntp * 2][0] = r0; bhi[ntp * 2][1] = r1;
                bhi[ntp * 2 + 1][0] = r2; bhi[ntp * 2 + 1][1] = r3;
                ldmatrix_x4(r0, r1, r2, r3, bLo + (uint32_t)ntp * 16u * LDA + koff);
                blo[ntp * 2][0] = r0; blo[ntp * 2][1] = r1;
                blo[ntp * 2 + 1][0] = r2; blo[ntp * 2 + 1][1] = r3;
            }

            #pragma unroll
            for (int mt = 0; mt < 2; ++mt)
                #pragma unroll
                for (int nt = 0; nt < 4; ++nt) {
                    mma_bf16(acc[mt][nt], ahi[mt][0], ahi[mt][1], ahi[mt][2], ahi[mt][3],
                             bhi[nt][0], bhi[nt][1]);
                    mma_bf16(acc[mt][nt], ahi[mt][0], ahi[mt][1], ahi[mt][2], ahi[mt][3],
                             blo[nt][0], blo[nt][1]);
                    mma_bf16(acc[mt][nt], alo[mt][0], alo[mt][1], alo[mt][2], alo[mt][3],
                             bhi[nt][0], bhi[nt][1]);
                }
        }
    }

    const int g  = lane >> 2;
    const int tg = lane & 3;
    const float* bp = bias + (size_t)grp * 64;
    float* Cp = C + (size_t)grp * gStrideC;
    #pragma unroll
    for (int mt = 0; mt < 2; ++mt)
        #pragma unroll
        for (int nt = 0; nt < 4; ++nt) {
            int col = wn * 32 + nt * 8 + tg * 2;
            float b0 = bp[col], b1 = bp[col + 1];
            int r0 = m0 + wm * 32 + mt * 16 + g;
            float2 o0 = make_float2(acc[mt][nt][0] + b0, acc[mt][nt][1] + b1);
            float2 o1 = make_float2(acc[mt][nt][2] + b0, acc[mt][nt][3] + b1);
            *(float2*)(Cp + (size_t)r0 * ldC + col)       = o0;
            *(float2*)(Cp + (size_t)(r0 + 8) * ldC + col) = o1;
        }
}

// ============================================================================
// Kernel 2: tensor-core flash attention, split-bf16, log2-domain softmax.
//   CTA = 128 q-rows of one (head,batch); 8 warps x 16 rows; chunks of 64 keys.
// SMEM regions (chunk phase):  KHI 0..9216, KLO 9216.., VTHI 18432.., VTLO 27648..
//   Q staging phase overlaps:  QHI 0..18432, QLO 18432..36864
// Row stride 144 B (64 bf16 + 16 pad) -> conflict-free ldmatrix.
// ============================================================================
#define LDS_ROW 144u
#define AKHI 0u
#define AKLO 9216u
#define AVHI 18432u
#define AVLO 27648u
#define AQHI 0u
#define AQLO 18432u

__global__ __launch_bounds__(256)
void attn_mma()
{
    __shared__ __align__(128) char smem[36864];
    const uint32_t sb = smem_u32(smem);
    const int tid  = threadIdx.x;
    const int lane = tid & 31;
    const int wid  = tid >> 5;
    const int g    = lane >> 2;
    const int tg   = lane & 3;
    const int hb   = blockIdx.y;
    const int hd   = hb >> 2;
    const int b    = hb & 3;
    const int q0   = blockIdx.x * 128;

    const float* Qg = g_ctx + ((size_t)hd * 8192 + b * 2048 + q0) * 64;
    const float* Kg = g_ctx + ((size_t)(16 + hd) * 8192 + (size_t)b * 2048) * 64;
    const float* Vg = g_ctx + ((size_t)(32 + hd) * 8192 + (size_t)b * 2048) * 64;

    // ---- stage Q (scaled by 8*log2e), split, ldmatrix into registers ----
    const float QSCALE = 11.5415603272f;   // 8 / ln(2)
    #pragma unroll
    for (int i = 0; i < 8; ++i) {
        int idx = tid + i * 256;            // 128 rows x 16 float4
        int row = idx >> 4;
        int c4  = idx & 15;
        float4 v = *(const float4*)(Qg + (size_t)row * 64 + c4 * 4);
        v.x *= QSCALE; v.y *= QSCALE; v.z *= QSCALE; v.w *= QSCALE;
        uint32_t h01, h23, l01, l23;
        split4(v, h01, h23, l01, l23);
        uint32_t off = (uint32_t)row * LDS_ROW + (uint32_t)c4 * 8u;
        *(uint2*)(smem + AQHI + off) = make_uint2(h01, h23);
        *(uint2*)(smem + AQLO + off) = make_uint2(l01, l23);
    }
    __syncthreads();

    uint32_t qhi[4][4], qlo[4][4];
    {
        const uint32_t qrow = (uint32_t)(wid * 16 + (lane & 7) + ((lane >> 3) & 1) * 8);
        const uint32_t kb   = (uint32_t)(lane >> 4) * 16u;
        const uint32_t aH = sb + AQHI + qrow * LDS_ROW + kb;
        const uint32_t aL = sb + AQLO + qrow * LDS_ROW + kb;
        #pragma unroll
        for (int t = 0; t < 4; ++t) {
            ldmatrix_x4(qhi[t][0], qhi[t][1], qhi[t][2], qhi[t][3], aH + t * 32u);
            ldmatrix_x4(qlo[t][0], qlo[t][1], qlo[t][2], qlo[t][3], aL + t * 32u);
        }
    }

    float mA = -1e30f, mB = -1e30f, lA = 0.f, lB = 0.f;
    float oacc[8][4];
    #pragma unroll
    for (int j = 0; j < 8; ++j)
        #pragma unroll
        for (int i = 0; i < 4; ++i) oacc[j][i] = 0.f;

    // B-fragment ldmatrix base offsets (shared by K and Vt reads)
    const uint32_t brow = (uint32_t)((lane & 7) + (lane >> 4) * 8);
    const uint32_t bkb  = (uint32_t)((lane >> 3) & 1) * 16u;

    for (int j0 = 0; j0 < 2048; j0 += 64) {
        __syncthreads();   // previous iteration's ldmatrix reads complete (also Q phase)

        // ---- load K chunk (natural) and V chunk (transposed), split bf16 ----
        #pragma unroll
        for (int i = 0; i < 4; ++i) {
            int idx = tid + i * 256;
            {   // K: row = key, 64 x 16 float4
                int row = idx >> 4;
                int c4  = idx & 15;
                float4 v = *(const float4*)(Kg + (size_t)(j0 + row) * 64 + c4 * 4);
                uint32_t h01, h23, l01, l23;
                split4(v, h01, h23, l01, l23);
                uint32_t off = (uint32_t)row * LDS_ROW + (uint32_t)c4 * 8u;
                *(uint2*)(smem + AKHI + off) = make_uint2(h01, h23);
                *(uint2*)(smem + AKLO + off) = make_uint2(l01, l23);
            }
            {   // V: transpose into [d][key]
                int key = idx & 63;
                int q4  = idx >> 6;
                float4 v = *(const float4*)(Vg + (size_t)(j0 + key) * 64 + q4 * 4);
                uint32_t h01, h23, l01, l23;
                split4(v, h01, h23, l01, l23);
                uint32_t o0 = (uint32_t)(q4 * 4) * LDS_ROW + (uint32_t)key * 2u;
                *(uint16_t*)(smem + AVHI + o0)                = (uint16_t)(h01 & 0xFFFF);
                *(uint16_t*)(smem + AVHI + o0 + LDS_ROW)      = (uint16_t)(h01 >> 16);
                *(uint16_t*)(smem + AVHI + o0 + 2 * LDS_ROW)  = (uint16_t)(h23 & 0xFFFF);
                *(uint16_t*)(smem + AVHI + o0 + 3 * LDS_ROW)  = (uint16_t)(h23 >> 16);
                *(uint16_t*)(smem + AVLO + o0)                = (uint16_t)(l01 & 0xFFFF);
                *(uint16_t*)(smem + AVLO + o0 + LDS_ROW)      = (uint16_t)(l01 >> 16);
                *(uint16_t*)(smem + AVLO + o0 + 2 * LDS_ROW)  = (uint16_t)(l23 & 0xFFFF);
                *(uint16_t*)(smem + AVLO + o0 + 3 * LDS_ROW)  = (uint16_t)(l23 >> 16);
            }
        }
        __syncthreads();

        // ---- S = Qscaled @ K^T (split 3-term), log2 units ----
        float sacc[8][4];
        #pragma unroll
        for (int j = 0; j < 8; ++j)
            #pragma unroll
            for (int i = 0; i < 4; ++i) sacc[j][i] = 0.f;

        #pragma unroll
        for (int td = 0; td < 4; ++td) {
            uint32_t bhi[8][2], blo[8][2];
            #pragma unroll
            for (int ntp = 0; ntp < 4; ++ntp) {
                uint32_t base = (uint32_t)(ntp * 16) * LDS_ROW + brow * LDS_ROW + bkb
                                + (uint32_t)td * 32u;
                uint32_t r0, r1, r2, r3;
                ldmatrix_x4(r0, r1, r2, r3, sb + AKHI + base);
                bhi[ntp * 2][0] = r0; bhi[ntp * 2][1] = r1;
                bhi[ntp * 2 + 1][0] = r2; bhi[ntp * 2 + 1][1] = r3;
                ldmatrix_x4(r0, r1, r2, r3, sb + AKLO + base);
                blo[ntp * 2][0] = r0; blo[ntp * 2][1] = r1;
                blo[ntp * 2 + 1][0] = r2; blo[ntp * 2 + 1][1] = r3;
            }
            #pragma unroll
            for (int nt = 0; nt < 8; ++nt) {
                mma_bf16(sacc[nt], qhi[td][0], qhi[td][1], qhi[td][2], qhi[td][3],
                         bhi[nt][0], bhi[nt][1]);
                mma_bf16(sacc[nt], qhi[td][0], qhi[td][1], qhi[td][2], qhi[td][3],
                         blo[nt][0], blo[nt][1]);
                mma_bf16(sacc[nt], qlo[td][0], qlo[td][1], qlo[td][2], qlo[td][3],
                         bhi[nt][0], bhi[nt][1]);
            }
        }

        // ---- online softmax (log2 domain, FFMA-only exp2) ----
        float rmA = -1e30f, rmB = -1e30f;
        #pragma unroll
        for (int j = 0; j < 8; ++j) {
            rmA = fmaxf(rmA, fmaxf(sacc[j][0], sacc[j][1]));
            rmB = fmaxf(rmB, fmaxf(sacc[j][2], sacc[j][3]));
        }
        rmA = fmaxf(rmA, __shfl_xor_sync(0xffffffffu, rmA, 1));
        rmA = fmaxf(rmA, __shfl_xor_sync(0xffffffffu, rmA, 2));
        rmB = fmaxf(rmB, __shfl_xor_sync(0xffffffffu, rmB, 1));
        rmB = fmaxf(rmB, __shfl_xor_sync(0xffffffffu, rmB, 2));

        float mnA = fmaxf(mA, rmA), mnB = fmaxf(mB, rmB);
        float corrA = exp2_fast(mA - mnA), corrB = exp2_fast(mB - mnB);

        float sumA = 0.f, sumB = 0.f;
        uint32_t phi[4][4], plo[4][4];
        #pragma unroll
        for (int j = 0; j < 8; ++j) {
            float p0 = exp2_fast(sacc[j][0] - mnA);
            float p1 = exp2_fast(sacc[j][1] - mnA);
            float p2 = exp2_fast(sacc[j][2] - mnB);
            float p3 = exp2_fast(sacc[j][3] - mnB);
            sumA += p0 + p1; sumB += p2 + p3;
            int t = j >> 1;
            int o = (j & 1) * 2;
            uint32_t h01 = pack_bf16x2(p0, p1);
            uint32_t h23 = pack_bf16x2(p2, p3);
            phi[t][o]     = h01;
            phi[t][o + 1] = h23;
            float r0 = p0 - __int_as_float(h01 << 16);
            float r1 = p1 - __int_as_float(h01 & 0xFFFF0000u);
            float r2 = p2 - __int_as_float(h23 << 16);
            float r3 = p3 - __int_as_float(h23 & 0xFFFF0000u);
            plo[t][o]     = pack_bf16x2(r0, r1);
            plo[t][o + 1] = pack_bf16x2(r2, r3);
        }
        sumA += __shfl_xor_sync(0xffffffffu, sumA, 1);
        sumA += __shfl_xor_sync(0xffffffffu, sumA, 2);
        sumB += __shfl_xor_sync(0xffffffffu, sumB, 1);
        sumB += __shfl_xor_sync(0xffffffffu, sumB, 2);

        lA = lA * corrA + sumA;
        lB = lB * corrB + sumB;
        mA = mnA; mB = mnB;

        #pragma unroll
        for (int j = 0; j < 8; ++j) {
            oacc[j][0] *= corrA; oacc[j][1] *= corrA;
            oacc[j][2] *= corrB; oacc[j][3] *= corrB;
        }

        // ---- O += P @ V (split 3-term) ----
        #pragma unroll
        for (int t = 0; t < 4; ++t) {
            uint32_t vhi[8][2], vlo[8][2];
            #pragma unroll
            for (int ntp = 0; ntp < 4; ++ntp) {
                uint32_t base = (uint32_t)(ntp * 16) * LDS_ROW + brow * LDS_ROW + bkb
                                + (uint32_t)t * 32u;
                uint32_t r0, r1, r2, r3;
                ldmatrix_x4(r0, r1, r2, r3, sb + AVHI + base);
                vhi[ntp * 2][0] = r0; vhi[ntp * 2][1] = r1;
                vhi[ntp * 2 + 1][0] = r2; vhi[ntp * 2 + 1][1] = r3;
                ldmatrix_x4(r0, r1, r2, r3, sb + AVLO + base);
                vlo[ntp * 2][0] = r0; vlo[ntp * 2][1] = r1;
                vlo[ntp * 2 + 1][0] = r2; vlo[ntp * 2 + 1][1] = r3;
            }
            #pragma unroll
            for (int nd = 0; nd < 8; ++nd) {
                mma_bf16(oacc[nd], phi[t][0], phi[t][1], phi[t][2], phi[t][3],
                         vhi[nd][0], vhi[nd][1]);
                mma_bf16(oacc[nd], phi[t][0], phi[t][1], phi[t][2], phi[t][3],
                         vlo[nd][0], vlo[nd][1]);
                mma_bf16(oacc[nd], plo[t][0], plo[t][1], plo[t][2], plo[t][3],
                         vhi[nd][0], vhi[nd][1]);
            }
        }
    }

    // ---- epilogue: O / l -> g_av[row][hd*64 + d] ----
    const float invA = 1.f / lA, invB = 1.f / lB;
    const int rowA = q0 + wid * 16 + g;
    const int rowB = rowA + 8;
    #pragma unroll
    for (int jd = 0; jd < 8; ++jd) {
        int col = hd * 64 + jd * 8 + tg * 2;
        *(float2*)(g_av + (size_t)(b * 2048 + rowA) * 1024 + col) =
            make_float2(oacc[jd][0] * invA, oacc[jd][1] * invA);
        *(float2*)(g_av + (size_t)(b * 2048 + rowB) * 1024 + col) =
            make_float2(oacc[jd][2] * invB, oacc[jd][3] * invB);
    }
}

// ============================================================================
extern "C" void kernel_launch(void* const* d_in, const int* in_sizes, int n_in,
                              void* d_out, int out_size)
{
    const float* x    = (const float*)d_in[0];   // (4, 2048, 1024)
    const float* Wqkv = (const float*)d_in[1];   // (48, 1024, 64)
    const float* bqkv = (const float*)d_in[2];   // (48, 64)
    const float* Wp   = (const float*)d_in[3];   // (1024, 1024)
    const float* bp   = (const float*)d_in[4];   // (1024,)
    float* out = (float*)d_out;                  // (4, 2048, 1024)

    float* g_wt_p;   cudaGetSymbolAddress((void**)&g_wt_p,  g_wt);
    float* g_ctx_p;  cudaGetSymbolAddress((void**)&g_ctx_p, g_ctx);
    float* g_av_p;   cudaGetSymbolAddress((void**)&g_av_p,  g_av);

    // 1) transpose Wqkv -> g_wt [48][64][1024]  (B must be K-major)
    transpose_w<<<dim3(32, 2, 48), dim3(32, 8)>>>(Wqkv);

    // 2) QKV: ctx[e] = x @ Wqkv[e] + bqkv[e]
    gemm_mma<<<dim3(64, 48), 256>>>(x, g_wt_p, bqkv, g_ctx_p,
                                    /*ldC=*/64, /*gStrideC=*/(size_t)8192 * 64);

    // 3) attention (tensor-core flash, split-bf16)
    attn_mma<<<dim3(16, 64), 256>>>();

    // 4) proj: out = av @ Wp^T + bp
    gemm_mma<<<dim3(64, 16), 256>>>(g_av_p, Wp, bp, out,
                                    /*ldC=*/1024, /*gStrideC=*/64);
}

// round 6
// speedup vs baseline: 2.9424x; 1.7406x over previous
#include <cuda_runtime.h>
#include <cuda_bf16.h>
#include <stdint.h>
#include <math.h>

// ============================================================================
// Scratch (device globals — no allocations allowed).
// ============================================================================
__device__ float g_ctx[48ull * 8192ull * 64ull];   // [e][row][h], ~100.7 MB
__device__ float g_av [8192ull * 1024ull];         // attention output, 33.5 MB
__device__ float g_wt [48ull * 64ull * 1024ull];   // Wqkv transposed [e][h][d]
// Pre-split attention operands (bf16 hi/lo). hb = head*4 + batch.
__device__ __nv_bfloat16 g_khi [16ull * 4 * 2048 * 64];   // [hb][l][d]
__device__ __nv_bfloat16 g_klo [16ull * 4 * 2048 * 64];
__device__ __nv_bfloat16 g_vthi[16ull * 4 * 64 * 2048];   // [hb][d][l]
__device__ __nv_bfloat16 g_vtlo[16ull * 4 * 64 * 2048];

// ============================================================================
// PTX helpers (sm_80-era ISA — compiles for plain compute_103)
// ============================================================================
__device__ __forceinline__ uint32_t smem_u32(const void* p) {
    uint32_t a;
    asm("{ .reg .u64 t; cvta.to.shared.u64 t, %1; cvt.u32.u64 %0, t; }"
        : "=r"(a) : "l"(p));
    return a;
}

__device__ __forceinline__ void ldmatrix_x4(uint32_t& r0, uint32_t& r1,
                                            uint32_t& r2, uint32_t& r3,
                                            uint32_t addr) {
    asm volatile("ldmatrix.sync.aligned.m8n8.x4.shared.b16 {%0,%1,%2,%3}, [%4];"
                 : "=r"(r0), "=r"(r1), "=r"(r2), "=r"(r3) : "r"(addr));
}

__device__ __forceinline__ void mma_bf16(float* c,
                                         uint32_t a0, uint32_t a1, uint32_t a2, uint32_t a3,
                                         uint32_t b0, uint32_t b1) {
    asm volatile("mma.sync.aligned.m16n8k16.row.col.f32.bf16.bf16.f32 "
                 "{%0,%1,%2,%3}, {%4,%5,%6,%7}, {%8,%9}, {%0,%1,%2,%3};"
                 : "+f"(c[0]), "+f"(c[1]), "+f"(c[2]), "+f"(c[3])
                 : "r"(a0), "r"(a1), "r"(a2), "r"(a3), "r"(b0), "r"(b1));
}

__device__ __forceinline__ void cp_async16(uint32_t dst, const void* src) {
    asm volatile("cp.async.cg.shared.global [%0], [%1], 16;"
                 :: "r"(dst), "l"(src) : "memory");
}
__device__ __forceinline__ void cp_commit() {
    asm volatile("cp.async.commit_group;" ::: "memory");
}
template <int N>
__device__ __forceinline__ void cp_wait() {
    asm volatile("cp.async.wait_group %0;" :: "n"(N) : "memory");
}

__device__ __forceinline__ uint32_t pack_bf16x2(float x, float y) {
    uint32_t r;
    asm("cvt.rn.bf16x2.f32 %0, %1, %2;" : "=r"(r) : "f"(y), "f"(x));
    return r;
}

// fast 2^t for t <= 0, FFMA/ALU only (no MUFU). rel err ~2.5e-6.
__device__ __forceinline__ float exp2_fast(float t) {
    float r = fmaxf(t, -30.f);
    float z = r + 12582912.f;
    int   i = __float_as_int(z);
    float f = r - (z - 12582912.f);
    float p = 1.33335581e-3f;
    p = fmaf(p, f, 9.61812911e-3f);
    p = fmaf(p, f, 5.55041087e-2f);
    p = fmaf(p, f, 2.40226507e-1f);
    p = fmaf(p, f, 6.93147181e-1f);
    p = fmaf(p, f, 1.0f);
    return p * __int_as_float((i + 127) << 23);
}

__device__ __forceinline__ void split4(float4 v, uint32_t& h01, uint32_t& h23,
                                       uint32_t& l01, uint32_t& l23) {
    h01 = pack_bf16x2(v.x, v.y);
    h23 = pack_bf16x2(v.z, v.w);
    float r0 = v.x - __int_as_float(h01 << 16);
    float r1 = v.y - __int_as_float(h01 & 0xFFFF0000u);
    float r2 = v.z - __int_as_float(h23 << 16);
    float r3 = v.w - __int_as_float(h23 & 0xFFFF0000u);
    l01 = pack_bf16x2(r0, r1);
    l23 = pack_bf16x2(r2, r3);
}

// ============================================================================
// Kernel 0: transpose Wqkv [48][1024][64] -> g_wt [48][64][1024]
// ============================================================================
__global__ void transpose_w(const float* __restrict__ W) {
    __shared__ float t[32][33];
    const int e  = blockIdx.z;
    const int k0 = blockIdx.x * 32;
    const int h0 = blockIdx.y * 32;
    const int tx = threadIdx.x, ty = threadIdx.y;
    #pragma unroll
    for (int i = 0; i < 32; i += 8)
        t[ty + i][tx] = W[(size_t)e * 65536 + (size_t)(k0 + ty + i) * 64 + h0 + tx];
    __syncthreads();
    #pragma unroll
    for (int i = 0; i < 32; i += 8)
        g_wt[(size_t)e * 65536 + (size_t)(h0 + ty + i) * 1024 + k0 + tx] = t[tx][ty + i];
}

// ============================================================================
// Kernel 1: split-bf16 tensor-core GEMM (mma.sync) — unchanged, proven.
// ============================================================================
#define LDA   80u
#define SA_HI 0u
#define SA_LO 10240u
#define SB_HI 20480u
#define SB_LO 25600u

__global__ __launch_bounds__(256)
void gemm_mma(const float* __restrict__ A, const float* __restrict__ B,
              const float* __restrict__ bias, float* __restrict__ C,
              int ldC, size_t gStrideC)
{
    __shared__ char smem[30720];
    const uint32_t sb  = smem_u32(smem);
    const int tid  = threadIdx.x;
    const int lane = tid & 31;
    const int wid  = tid >> 5;
    const int wm   = wid & 3;
    const int wn   = wid >> 2;
    const int m0   = blockIdx.x * 128;
    const int grp  = blockIdx.y;

    const float* Bg = B + (size_t)grp * 64 * 1024;

    float acc[2][4][4];
    #pragma unroll
    for (int mt = 0; mt < 2; ++mt)
        #pragma unroll
        for (int nt = 0; nt < 4; ++nt)
            #pragma unroll
            for (int i = 0; i < 4; ++i) acc[mt][nt][i] = 0.f;

    const int a_row = wm * 32 + (lane & 7) + ((lane >> 3) & 1) * 8;
    const uint32_t a_kb = (uint32_t)(lane >> 4) * 16u;
    const uint32_t aHi = sb + SA_HI + (uint32_t)a_row * LDA + a_kb;
    const uint32_t aLo = sb + SA_LO + (uint32_t)a_row * LDA + a_kb;

    const int b_row = wn * 32 + (lane & 7) + (lane >> 4) * 8;
    const uint32_t b_kb = (uint32_t)((lane >> 3) & 1) * 16u;
    const uint32_t bHi = sb + SB_HI + (uint32_t)b_row * LDA + b_kb;
    const uint32_t bLo = sb + SB_LO + (uint32_t)b_row * LDA + b_kb;

    for (int k0 = 0; k0 < 1024; k0 += 32) {
        __syncthreads();

        #pragma unroll
        for (int i = 0; i < 4; ++i) {
            int idx = tid + i * 256;
            int row = idx >> 3;
            int c4  = idx & 7;
            float4 v = *(const float4*)(A + (size_t)(m0 + row) * 1024 + k0 + c4 * 4);
            uint32_t h01, h23, l01, l23;
            split4(v, h01, h23, l01, l23);
            uint32_t off = (uint32_t)row * LDA + (uint32_t)c4 * 8u;
            *(uint2*)(smem + SA_HI + off) = make_uint2(h01, h23);
            *(uint2*)(smem + SA_LO + off) = make_uint2(l01, l23);
        }
        #pragma unroll
        for (int i = 0; i < 2; ++i) {
            int idx = tid + i * 256;
            int row = idx >> 3;
            int c4  = idx & 7;
            float4 v = *(const float4*)(Bg + (size_t)row * 1024 + k0 + c4 * 4);
            uint32_t h01, h23, l01, l23;
            split4(v, h01, h23, l01, l23);
            uint32_t off = (uint32_t)row * LDA + (uint32_t)c4 * 8u;
            *(uint2*)(smem + SB_HI + off) = make_uint2(h01, h23);
            *(uint2*)(smem + SB_LO + off) = make_uint2(l01, l23);
        }
        __syncthreads();

        #pragma unroll
        for (int ks = 0; ks < 2; ++ks) {
            const uint32_t koff = (uint32_t)ks * 32u;

            uint32_t ahi[2][4], alo[2][4];
            #pragma unroll
            for (int mt = 0; mt < 2; ++mt) {
                ldmatrix_x4(ahi[mt][0], ahi[mt][1], ahi[mt][2], ahi[mt][3],
                            aHi + (uint32_t)mt * 16u * LDA + koff);
                ldmatrix_x4(alo[mt][0], alo[mt][1], alo[mt][2], alo[mt][3],
                            aLo + (uint32_t)mt * 16u * LDA + koff);
            }
            uint32_t bhi[4][2], blo[4][2];
            #pragma unroll
            for (int ntp = 0; ntp < 2; ++ntp) {
                uint32_t r0, r1, r2, r3;
                ldmatrix_x4(r0, r1, r2, r3, bHi + (uint32_t)ntp * 16u * LDA + koff);
                bhi[ntp * 2][0] = r0; bhi[ntp * 2][1] = r1;
                bhi[ntp * 2 + 1][0] = r2; bhi[ntp * 2 + 1][1] = r3;
                ldmatrix_x4(r0, r1, r2, r3, bLo + (uint32_t)ntp * 16u * LDA + koff);
                blo[ntp * 2][0] = r0; blo[ntp * 2][1] = r1;
                blo[ntp * 2 + 1][0] = r2; blo[ntp * 2 + 1][1] = r3;
            }

            #pragma unroll
            for (int mt = 0; mt < 2; ++mt)
                #pragma unroll
                for (int nt = 0; nt < 4; ++nt) {
                    mma_bf16(acc[mt][nt], ahi[mt][0], ahi[mt][1], ahi[mt][2], ahi[mt][3],
                             bhi[nt][0], bhi[nt][1]);
                    mma_bf16(acc[mt][nt], ahi[mt][0], ahi[mt][1], ahi[mt][2], ahi[mt][3],
                             blo[nt][0], blo[nt][1]);
                    mma_bf16(acc[mt][nt], alo[mt][0], alo[mt][1], alo[mt][2], alo[mt][3],
                             bhi[nt][0], bhi[nt][1]);
                }
        }
    }

    const int g  = lane >> 2;
    const int tg = lane & 3;
    const float* bp = bias + (size_t)grp * 64;
    float* Cp = C + (size_t)grp * gStrideC;
    #pragma unroll
    for (int mt = 0; mt < 2; ++mt)
        #pragma unroll
        for (int nt = 0; nt < 4; ++nt) {
            int col = wn * 32 + nt * 8 + tg * 2;
            float b0 = bp[col], b1 = bp[col + 1];
            int r0 = m0 + wm * 32 + mt * 16 + g;
            float2 o0 = make_float2(acc[mt][nt][0] + b0, acc[mt][nt][1] + b1);
            float2 o1 = make_float2(acc[mt][nt][2] + b0, acc[mt][nt][3] + b1);
            *(float2*)(Cp + (size_t)r0 * ldC + col)       = o0;
            *(float2*)(Cp + (size_t)(r0 + 8) * ldC + col) = o1;
        }
}

// ============================================================================
// Kernel 1.5: prep K/V — split to bf16 hi/lo once; V also transposed.
//   One CTA: 64 keys x 64 d for one hb. grid (32, 64).
// ============================================================================
__global__ __launch_bounds__(256)
void prep_kv()
{
    __shared__ __nv_bfloat16 vt_hi[64 * 72];   // [d][key], stride 72 elems (144B)
    __shared__ __nv_bfloat16 vt_lo[64 * 72];

    const int tid = threadIdx.x;
    const int hb  = blockIdx.y;
    const int hd  = hb >> 2;
    const int b   = hb & 3;
    const int l0  = blockIdx.x * 64;

    const float* Kg = g_ctx + ((size_t)(16 + hd) * 8192 + (size_t)b * 2048 + l0) * 64;
    const float* Vg = g_ctx + ((size_t)(32 + hd) * 8192 + (size_t)b * 2048 + l0) * 64;

    // --- K: straight split, coalesced in and out ---
    #pragma unroll
    for (int i = 0; i < 4; ++i) {
        int idx = tid + i * 256;            // < 1024 : 64 rows x 16 float4
        int row = idx >> 4;
        int c4  = idx & 15;
        float4 v = *(const float4*)(Kg + (size_t)row * 64 + c4 * 4);
        uint32_t h01, h23, l01, l23;
        split4(v, h01, h23, l01, l23);
        size_t off = ((size_t)hb * 2048 + l0 + row) * 64 + c4 * 4;
        *(uint2*)&g_khi[off] = make_uint2(h01, h23);
        *(uint2*)&g_klo[off] = make_uint2(l01, l23);
    }

    // --- V: split + transpose via smem ---
    #pragma unroll
    for (int i = 0; i < 4; ++i) {
        int idx = tid + i * 256;
        int key = idx >> 4;
        int c4  = idx & 15;
        float4 v = *(const float4*)(Vg + (size_t)key * 64 + c4 * 4);
        uint32_t h01, h23, l01, l23;
        split4(v, h01, h23, l01, l23);
        int d = c4 * 4;
        vt_hi[(d + 0) * 72 + key] = __ushort_as_bfloat16((uint16_t)(h01 & 0xFFFF));
        vt_hi[(d + 1) * 72 + key] = __ushort_as_bfloat16((uint16_t)(h01 >> 16));
        vt_hi[(d + 2) * 72 + key] = __ushort_as_bfloat16((uint16_t)(h23 & 0xFFFF));
        vt_hi[(d + 3) * 72 + key] = __ushort_as_bfloat16((uint16_t)(h23 >> 16));
        vt_lo[(d + 0) * 72 + key] = __ushort_as_bfloat16((uint16_t)(l01 & 0xFFFF));
        vt_lo[(d + 1) * 72 + key] = __ushort_as_bfloat16((uint16_t)(l01 >> 16));
        vt_lo[(d + 2) * 72 + key] = __ushort_as_bfloat16((uint16_t)(l23 & 0xFFFF));
        vt_lo[(d + 3) * 72 + key] = __ushort_as_bfloat16((uint16_t)(l23 >> 16));
    }
    __syncthreads();

    #pragma unroll
    for (int i = 0; i < 2; ++i) {
        int idx = tid + i * 256;            // < 512 : 64 d-rows x 8 granules of 16B
        int d   = idx >> 3;
        int c   = idx & 7;
        uint4 hv = *(uint4*)&vt_hi[d * 72 + c * 8];
        uint4 lv = *(uint4*)&vt_lo[d * 72 + c * 8];
        size_t off = ((size_t)hb * 64 + d) * 2048 + l0 + c * 8;
        *(uint4*)&g_vthi[off] = hv;
        *(uint4*)&g_vtlo[off] = lv;
    }
}

// ============================================================================
// Kernel 2: tensor-core flash attention. Pre-split bf16 K/V via cp.async,
//   double-buffered. 128 q-rows per CTA, 8 warps, 64-key chunks.
// Stage layout (36864 B each, 2 stages):
//   KHI 0, KLO 9216, VHI 18432, VLO 27648. Row stride 144 B.
// Q staged once (fp32 -> split) into stage area before the loop.
// ============================================================================
#define LDS_ROW 144u
#define ST_KHI 0u
#define ST_KLO 9216u
#define ST_VHI 18432u
#define ST_VLO 27648u
#define STAGE_BYTES 36864u
#define ATTN_SMEM (2 * 36864)

__global__ __launch_bounds__(256)
void attn_mma()
{
    extern __shared__ __align__(128) char smem[];
    const uint32_t sb = smem_u32(smem);
    const int tid  = threadIdx.x;
    const int lane = tid & 31;
    const int wid  = tid >> 5;
    const int g    = lane >> 2;
    const int tg   = lane & 3;
    const int hb   = blockIdx.y;
    const int hd   = hb >> 2;
    const int b    = hb & 3;
    const int q0   = blockIdx.x * 128;

    const float* Qg = g_ctx + ((size_t)hd * 8192 + b * 2048 + q0) * 64;
    const __nv_bfloat16* Khi = g_khi  + (size_t)hb * 2048 * 64;
    const __nv_bfloat16* Klo = g_klo  + (size_t)hb * 2048 * 64;
    const __nv_bfloat16* Vhi = g_vthi + (size_t)hb * 64 * 2048;
    const __nv_bfloat16* Vlo = g_vtlo + (size_t)hb * 64 * 2048;

    // ---- stage Q (scaled by 8*log2e), split, extract fragments ----
    const float QSCALE = 11.5415603272f;   // 8 / ln(2)
    #pragma unroll
    for (int i = 0; i < 8; ++i) {
        int idx = tid + i * 256;
        int row = idx >> 4;
        int c4  = idx & 15;
        float4 v = *(const float4*)(Qg + (size_t)row * 64 + c4 * 4);
        v.x *= QSCALE; v.y *= QSCALE; v.z *= QSCALE; v.w *= QSCALE;
        uint32_t h01, h23, l01, l23;
        split4(v, h01, h23, l01, l23);
        uint32_t off = (uint32_t)row * LDS_ROW + (uint32_t)c4 * 8u;
        *(uint2*)(smem + off)         = make_uint2(h01, h23);
        *(uint2*)(smem + 18432 + off) = make_uint2(l01, l23);
    }
    __syncthreads();

    uint32_t qhi[4][4], qlo[4][4];
    {
        const uint32_t qrow = (uint32_t)(wid * 16 + (lane & 7) + ((lane >> 3) & 1) * 8);
        const uint32_t kb   = (uint32_t)(lane >> 4) * 16u;
        const uint32_t aH = sb + qrow * LDS_ROW + kb;
        const uint32_t aL = sb + 18432 + qrow * LDS_ROW + kb;
        #pragma unroll
        for (int t = 0; t < 4; ++t) {
            ldmatrix_x4(qhi[t][0], qhi[t][1], qhi[t][2], qhi[t][3], aH + t * 32u);
            ldmatrix_x4(qlo[t][0], qlo[t][1], qlo[t][2], qlo[t][3], aL + t * 32u);
        }
    }
    __syncthreads();   // Q reads complete — smem free for cp.async stages

    float mA = -1e30f, mB = -1e30f, lA = 0.f, lB = 0.f;
    float oacc[8][4];
    #pragma unroll
    for (int j = 0; j < 8; ++j)
        #pragma unroll
        for (int i = 0; i < 4; ++i) oacc[j][i] = 0.f;

    const uint32_t brow = (uint32_t)((lane & 7) + (lane >> 4) * 8);
    const uint32_t bkb  = (uint32_t)((lane >> 3) & 1) * 16u;

    // cp.async issue of one 64-key chunk into stage base `stg`
    const int cp_row = tid >> 3;     // 0..31 (x2 iters -> 0..63)
    const int cp_c   = tid & 7;      // 16B granule
    auto issue = [&](int j0, uint32_t stg) {
        #pragma unroll
        for (int i = 0; i < 2; ++i) {
            int row = cp_row + i * 32;
            uint32_t doff = stg + (uint32_t)row * LDS_ROW + (uint32_t)cp_c * 16u;
            const __nv_bfloat16* skh = Khi + ((size_t)(j0 + row)) * 64 + cp_c * 8;
            const __nv_bfloat16* skl = Klo + ((size_t)(j0 + row)) * 64 + cp_c * 8;
            const __nv_bfloat16* svh = Vhi + ((size_t)row) * 2048 + j0 + cp_c * 8;
            const __nv_bfloat16* svl = Vlo + ((size_t)row) * 2048 + j0 + cp_c * 8;
            cp_async16(doff + ST_KHI, skh);
            cp_async16(doff + ST_KLO, skl);
            cp_async16(doff + ST_VHI, svh);
            cp_async16(doff + ST_VLO, svl);
        }
        cp_commit();
    };

    issue(0, sb);   // chunk 0 -> stage 0

    for (int j = 0; j < 32; ++j) {
        const uint32_t stg = sb + (uint32_t)(j & 1) * STAGE_BYTES;

        if (j < 31) {
            issue((j + 1) * 64, sb + (uint32_t)((j + 1) & 1) * STAGE_BYTES);
            cp_wait<1>();
        } else {
            cp_wait<0>();
        }
        __syncthreads();

        // ---- S = Qscaled @ K^T (split 3-term), log2 units ----
        float sacc[8][4];
        #pragma unroll
        for (int jj = 0; jj < 8; ++jj)
            #pragma unroll
            for (int i = 0; i < 4; ++i) sacc[jj][i] = 0.f;

        #pragma unroll
        for (int td = 0; td < 4; ++td) {
            uint32_t bhi[8][2], blo[8][2];
            #pragma unroll
            for (int ntp = 0; ntp < 4; ++ntp) {
                uint32_t base = (uint32_t)(ntp * 16) * LDS_ROW + brow * LDS_ROW + bkb
                                + (uint32_t)td * 32u;
                uint32_t r0, r1, r2, r3;
                ldmatrix_x4(r0, r1, r2, r3, stg + ST_KHI + base);
                bhi[ntp * 2][0] = r0; bhi[ntp * 2][1] = r1;
                bhi[ntp * 2 + 1][0] = r2; bhi[ntp * 2 + 1][1] = r3;
                ldmatrix_x4(r0, r1, r2, r3, stg + ST_KLO + base);
                blo[ntp * 2][0] = r0; blo[ntp * 2][1] = r1;
                blo[ntp * 2 + 1][0] = r2; blo[ntp * 2 + 1][1] = r3;
            }
            #pragma unroll
            for (int nt = 0; nt < 8; ++nt) {
                mma_bf16(sacc[nt], qhi[td][0], qhi[td][1], qhi[td][2], qhi[td][3],
                         bhi[nt][0], bhi[nt][1]);
                mma_bf16(sacc[nt], qhi[td][0], qhi[td][1], qhi[td][2], qhi[td][3],
                         blo[nt][0], blo[nt][1]);
                mma_bf16(sacc[nt], qlo[td][0], qlo[td][1], qlo[td][2], qlo[td][3],
                         bhi[nt][0], bhi[nt][1]);
            }
        }

        // ---- online softmax (log2 domain) ----
        float rmA = -1e30f, rmB = -1e30f;
        #pragma unroll
        for (int jj = 0; jj < 8; ++jj) {
            rmA = fmaxf(rmA, fmaxf(sacc[jj][0], sacc[jj][1]));
            rmB = fmaxf(rmB, fmaxf(sacc[jj][2], sacc[jj][3]));
        }
        rmA = fmaxf(rmA, __shfl_xor_sync(0xffffffffu, rmA, 1));
        rmA = fmaxf(rmA, __shfl_xor_sync(0xffffffffu, rmA, 2));
        rmB = fmaxf(rmB, __shfl_xor_sync(0xffffffffu, rmB, 1));
        rmB = fmaxf(rmB, __shfl_xor_sync(0xffffffffu, rmB, 2));

        float mnA = fmaxf(mA, rmA), mnB = fmaxf(mB, rmB);
        float corrA = exp2_fast(mA - mnA), corrB = exp2_fast(mB - mnB);

        float sumA = 0.f, sumB = 0.f;
        uint32_t phi[4][4], plo[4][4];
        #pragma unroll
        for (int jj = 0; jj < 8; ++jj) {
            float p0 = exp2_fast(sacc[jj][0] - mnA);
            float p1 = exp2_fast(sacc[jj][1] - mnA);
            float p2 = exp2_fast(sacc[jj][2] - mnB);
            float p3 = exp2_fast(sacc[jj][3] - mnB);
            sumA += p0 + p1; sumB += p2 + p3;
            int t = jj >> 1;
            int o = (jj & 1) * 2;
            uint32_t h01 = pack_bf16x2(p0, p1);
            uint32_t h23 = pack_bf16x2(p2, p3);
            phi[t][o]     = h01;
            phi[t][o + 1] = h23;
            float r0 = p0 - __int_as_float(h01 << 16);
            float r1 = p1 - __int_as_float(h01 & 0xFFFF0000u);
            float r2 = p2 - __int_as_float(h23 << 16);
            float r3 = p3 - __int_as_float(h23 & 0xFFFF0000u);
            plo[t][o]     = pack_bf16x2(r0, r1);
            plo[t][o + 1] = pack_bf16x2(r2, r3);
        }
        sumA += __shfl_xor_sync(0xffffffffu, sumA, 1);
        sumA += __shfl_xor_sync(0xffffffffu, sumA, 2);
        sumB += __shfl_xor_sync(0xffffffffu, sumB, 1);
        sumB += __shfl_xor_sync(0xffffffffu, sumB, 2);

        lA = lA * corrA + sumA;
        lB = lB * corrB + sumB;
        mA = mnA; mB = mnB;

        #pragma unroll
        for (int jj = 0; jj < 8; ++jj) {
            oacc[jj][0] *= corrA; oacc[jj][1] *= corrA;
            oacc[jj][2] *= corrB; oacc[jj][3] *= corrB;
        }

        // ---- O += P @ V (split 3-term) ----
        #pragma unroll
        for (int t = 0; t < 4; ++t) {
            uint32_t vhi[8][2], vlo[8][2];
            #pragma unroll
            for (int ntp = 0; ntp < 4; ++ntp) {
                uint32_t base = (uint32_t)(ntp * 16) * LDS_ROW + brow * LDS_ROW + bkb
                                + (uint32_t)t * 32u;
                uint32_t r0, r1, r2, r3;
                ldmatrix_x4(r0, r1, r2, r3, stg + ST_VHI + base);
                vhi[ntp * 2][0] = r0; vhi[ntp * 2][1] = r1;
                vhi[ntp * 2 + 1][0] = r2; vhi[ntp * 2 + 1][1] = r3;
                ldmatrix_x4(r0, r1, r2, r3, stg + ST_VLO + base);
                vlo[ntp * 2][0] = r0; vlo[ntp * 2][1] = r1;
                vlo[ntp * 2 + 1][0] = r2; vlo[ntp * 2 + 1][1] = r3;
            }
            #pragma unroll
            for (int nd = 0; nd < 8; ++nd) {
                mma_bf16(oacc[nd], phi[t][0], phi[t][1], phi[t][2], phi[t][3],
                         vhi[nd][0], vhi[nd][1]);
                mma_bf16(oacc[nd], phi[t][0], phi[t][1], phi[t][2], phi[t][3],
                         vlo[nd][0], vlo[nd][1]);
                mma_bf16(oacc[nd], plo[t][0], plo[t][1], plo[t][2], plo[t][3],
                         vhi[nd][0], vhi[nd][1]);
            }
        }

        __syncthreads();   // all reads of this stage done before reuse
    }

    // ---- epilogue ----
    const float invA = 1.f / lA, invB = 1.f / lB;
    const int rowA = q0 + wid * 16 + g;
    const int rowB = rowA + 8;
    #pragma unroll
    for (int jd = 0; jd < 8; ++jd) {
        int col = hd * 64 + jd * 8 + tg * 2;
        *(float2*)(g_av + (size_t)(b * 2048 + rowA) * 1024 + col) =
            make_float2(oacc[jd][0] * invA, oacc[jd][1] * invA);
        *(float2*)(g_av + (size_t)(b * 2048 + rowB) * 1024 + col) =
            make_float2(oacc[jd][2] * invB, oacc[jd][3] * invB);
    }
}

// ============================================================================
extern "C" void kernel_launch(void* const* d_in, const int* in_sizes, int n_in,
                              void* d_out, int out_size)
{
    const float* x    = (const float*)d_in[0];   // (4, 2048, 1024)
    const float* Wqkv = (const float*)d_in[1];   // (48, 1024, 64)
    const float* bqkv = (const float*)d_in[2];   // (48, 64)
    const float* Wp   = (const float*)d_in[3];   // (1024, 1024)
    const float* bp   = (const float*)d_in[4];   // (1024,)
    float* out = (float*)d_out;                  // (4, 2048, 1024)

    float* g_wt_p;   cudaGetSymbolAddress((void**)&g_wt_p,  g_wt);
    float* g_ctx_p;  cudaGetSymbolAddress((void**)&g_ctx_p, g_ctx);
    float* g_av_p;   cudaGetSymbolAddress((void**)&g_av_p,  g_av);

    static int smem_set = 0;
    if (!smem_set) {
        cudaFuncSetAttribute(attn_mma, cudaFuncAttributeMaxDynamicSharedMemorySize,
                             ATTN_SMEM);
        smem_set = 1;
    }

    // 1) transpose Wqkv -> g_wt [48][64][1024]
    transpose_w<<<dim3(32, 2, 48), dim3(32, 8)>>>(Wqkv);

    // 2) QKV: ctx[e] = x @ Wqkv[e] + bqkv[e]
    gemm_mma<<<dim3(64, 48), 256>>>(x, g_wt_p, bqkv, g_ctx_p,
                                    /*ldC=*/64, /*gStrideC=*/(size_t)8192 * 64);

    // 2.5) pre-split K/V to bf16 hi/lo (V transposed)
    prep_kv<<<dim3(32, 64), 256>>>();

    // 3) attention (cp.async double-buffered, pre-split operands)
    attn_mma<<<dim3(16, 64), 256, ATTN_SMEM>>>();

    // 4) proj: out = av @ Wp^T + bp
    gemm_mma<<<dim3(64, 16), 256>>>(g_av_p, Wp, bp, out,
                                    /*ldC=*/1024, /*gStrideC=*/64);
}